// round 4
// baseline (speedup 1.0000x reference)
#include <cuda_runtime.h>
#include <cuda_bf16.h>
#include <math.h>

#define N_NODES 100000
#define N_EDGES 1600000
#define F_IN   128
#define H1     200
#define H2     50
#define C_OUT  10
#define MAXDEG 128

typedef unsigned long long ull;

#define FMA_F32X2(c, a, b) \
    asm("fma.rn.f32x2 %0, %1, %2, %0;" : "+l"(c) : "l"(a), "l"(b))
#define SPLAT_F32X2(d, s) \
    asm("mov.b64 %0, {%1, %1};" : "=l"(d) : "r"(__float_as_uint(s)))

__device__ __forceinline__ float f32x2_lo(ull v) {
    return __uint_as_float((unsigned)(v & 0xffffffffu));
}
__device__ __forceinline__ float f32x2_hi(ull v) {
    return __uint_as_float((unsigned)(v >> 32));
}

// ---------------- scratch -----------------------------------------------------
__device__ int   g_cnt[N_NODES];
__device__ int   g_bucket[(size_t)N_NODES * MAXDEG];
__device__ float g_agg1[(size_t)N_NODES * F_IN];
__device__ float g_h1  [(size_t)N_NODES * H1];
__device__ float g_agg2[(size_t)N_NODES * H1];
__device__ float g_h2  [(size_t)N_NODES * H2];
__device__ float g_agg3[(size_t)N_NODES * H2];

// ---------------- bucket build ------------------------------------------------
__global__ void zero_cnt_kernel() {
    int i = blockIdx.x * blockDim.x + threadIdx.x;
    if (i < N_NODES) g_cnt[i] = 0;
}

__global__ void bucket_build_kernel(const int* __restrict__ src,
                                    const int* __restrict__ dst) {
    int e = blockIdx.x * blockDim.x + threadIdx.x;
    if (e >= N_EDGES) return;
    int d = dst[e];
    int p = atomicAdd(&g_cnt[d], 1);
    if (p < MAXDEG) g_bucket[(size_t)d * MAXDEG + p] = src[e];
}

// ---------------- aggregation: warp/node, float2 gather, 4-edge MLP ----------
template <int F>
__global__ void agg_kernel(const float* __restrict__ x, float* __restrict__ agg) {
    constexpr int C2 = F / 2;
    constexpr int RV = (C2 + 31) / 32;

    int gwarp = (blockIdx.x * blockDim.x + threadIdx.x) >> 5;
    int lane  = threadIdx.x & 31;
    if (gwarp >= N_NODES) return;

    int c = g_cnt[gwarp];
    if (c > MAXDEG) c = MAXDEG;

    float2 m[RV];
#pragma unroll
    for (int r = 0; r < RV; r++) { m[r].x = -INFINITY; m[r].y = -INFINITY; }

    const int* bk = g_bucket + (size_t)gwarp * MAXDEG;
    int i = 0;
    for (; i + 3 < c; i += 4) {
        int s0 = bk[i], s1 = bk[i + 1], s2 = bk[i + 2], s3 = bk[i + 3];
        const float2* r0 = (const float2*)(x + (size_t)s0 * F);
        const float2* r1 = (const float2*)(x + (size_t)s1 * F);
        const float2* r2 = (const float2*)(x + (size_t)s2 * F);
        const float2* r3 = (const float2*)(x + (size_t)s3 * F);
#pragma unroll
        for (int r = 0; r < RV; r++) {
            int ch = lane + r * 32;
            if (ch < C2) {
                float2 v0 = r0[ch], v1 = r1[ch], v2 = r2[ch], v3 = r3[ch];
                m[r].x = fmaxf(m[r].x, fmaxf(fmaxf(v0.x, v1.x), fmaxf(v2.x, v3.x)));
                m[r].y = fmaxf(m[r].y, fmaxf(fmaxf(v0.y, v1.y), fmaxf(v2.y, v3.y)));
            }
        }
    }
    for (; i < c; i++) {
        const float2* r0 = (const float2*)(x + (size_t)bk[i] * F);
#pragma unroll
        for (int r = 0; r < RV; r++) {
            int ch = lane + r * 32;
            if (ch < C2) {
                float2 v0 = r0[ch];
                m[r].x = fmaxf(m[r].x, v0.x);
                m[r].y = fmaxf(m[r].y, v0.y);
            }
        }
    }

    float2* out = (float2*)(agg + (size_t)gwarp * F);
#pragma unroll
    for (int r = 0; r < RV; r++) {
        int ch = lane + r * 32;
        if (ch < C2) out[ch] = (c == 0) ? make_float2(0.f, 0.f) : m[r];
    }
}

// ---------------- dual GEMM 128x128, FFMA2, double-buffered -----------------
__global__ __launch_bounds__(256, 2)
void gemm128_dual(const float* __restrict__ A1, const float* __restrict__ A2,
                  const float* __restrict__ W1, const float* __restrict__ W2,
                  const float* __restrict__ bias, float* __restrict__ out,
                  int M, int K, int NN) {
    constexpr int BM = 128, BN = 128, BK = 8, PAD = 4;
    __shared__ float As[2][BK][BM + PAD];
    __shared__ float Ws[2][BK][BN + PAD];

    int tid = threadIdx.x;
    int tx = tid & 15;
    int ty = tid >> 4;
    int rowBase = blockIdx.y * BM;
    int colBase = blockIdx.x * BN;

    int ar = tid >> 1;
    int ak = (tid & 1) * 4;
    int wk = tid >> 5;
    int wc = (tid & 31) * 4;

    int aRow = rowBase + ar;
    int wCol = colBase + wc;
    bool aOK = aRow < M;
    bool wOK = wCol < NN;

    ull acc[4][8];
#pragma unroll
    for (int p = 0; p < 4; p++)
#pragma unroll
        for (int j = 0; j < 8; j++) acc[p][j] = 0ull;

    const int ntiles = 2 * K / BK;

    // prologue: load tile 0 -> buffer 0
    {
        float4 va = make_float4(0.f, 0.f, 0.f, 0.f);
        float4 vw = make_float4(0.f, 0.f, 0.f, 0.f);
        if (aOK) va = *(const float4*)(A1 + (size_t)aRow * K + ak);
        if (wOK) vw = *(const float4*)(W1 + (size_t)wk * NN + wCol);
        As[0][ak + 0][ar] = va.x; As[0][ak + 1][ar] = va.y;
        As[0][ak + 2][ar] = va.z; As[0][ak + 3][ar] = va.w;
        *(float4*)&Ws[0][wk][wc] = vw;
    }
    __syncthreads();

    for (int t = 0; t < ntiles; t++) {
        int buf = t & 1;
        bool hasNext = (t + 1) < ntiles;

        float4 na = make_float4(0.f, 0.f, 0.f, 0.f);
        float4 nw = make_float4(0.f, 0.f, 0.f, 0.f);
        if (hasNext) {
            int kt = (t + 1) * BK;
            const float* A; const float* W; int ko;
            if (kt < K) { A = A1; W = W1; ko = kt; }
            else        { A = A2; W = W2; ko = kt - K; }
            if (aOK) na = *(const float4*)(A + (size_t)aRow * K + ko + ak);
            if (wOK) nw = *(const float4*)(W + (size_t)(ko + wk) * NN + wCol);
        }

#pragma unroll
        for (int kk = 0; kk < BK; kk++) {
            ulonglong2 la0 = *(const ulonglong2*)&As[buf][kk][ty * 8];
            ulonglong2 la1 = *(const ulonglong2*)&As[buf][kk][ty * 8 + 4];
            ull a2[4] = {la0.x, la0.y, la1.x, la1.y};

            float4 w0 = *(const float4*)&Ws[buf][kk][tx * 8];
            float4 w1 = *(const float4*)&Ws[buf][kk][tx * 8 + 4];
            float wv[8] = {w0.x, w0.y, w0.z, w0.w, w1.x, w1.y, w1.z, w1.w};
            ull w2[8];
#pragma unroll
            for (int j = 0; j < 8; j++) SPLAT_F32X2(w2[j], wv[j]);

#pragma unroll
            for (int p = 0; p < 4; p++)
#pragma unroll
                for (int j = 0; j < 8; j++)
                    FMA_F32X2(acc[p][j], a2[p], w2[j]);
        }

        if (hasNext) {
            int nb = buf ^ 1;
            As[nb][ak + 0][ar] = na.x; As[nb][ak + 1][ar] = na.y;
            As[nb][ak + 2][ar] = na.z; As[nb][ak + 3][ar] = na.w;
            *(float4*)&Ws[nb][wk][wc] = nw;
        }
        __syncthreads();
    }

#pragma unroll
    for (int p = 0; p < 4; p++) {
#pragma unroll
        for (int half = 0; half < 2; half++) {
            int row = rowBase + ty * 8 + p * 2 + half;
            if (row >= M) continue;
#pragma unroll
            for (int jv = 0; jv < 8; jv += 4) {
                int col = colBase + tx * 8 + jv;
                if (col < NN) {
                    float4 bv = *(const float4*)(bias + col);
                    float4 o;
                    o.x = (half ? f32x2_hi(acc[p][jv + 0]) : f32x2_lo(acc[p][jv + 0])) + bv.x;
                    o.y = (half ? f32x2_hi(acc[p][jv + 1]) : f32x2_lo(acc[p][jv + 1])) + bv.y;
                    o.z = (half ? f32x2_hi(acc[p][jv + 2]) : f32x2_lo(acc[p][jv + 2])) + bv.z;
                    o.w = (half ? f32x2_hi(acc[p][jv + 3]) : f32x2_lo(acc[p][jv + 3])) + bv.w;
                    *(float4*)(out + (size_t)row * NN + col) = o;
                }
            }
        }
    }
}

// ---------------- dual GEMM 128x64, FFMA2, double-buffered ------------------
__global__ __launch_bounds__(256, 2)
void gemm64_dual(const float* __restrict__ A1, const float* __restrict__ A2,
                 const float* __restrict__ W1, const float* __restrict__ W2,
                 const float* __restrict__ bias, float* __restrict__ out,
                 int M, int K, int NN) {
    constexpr int BM = 128, BN = 64, BK = 8, PAD = 4;
    __shared__ float As[2][BK][BM + PAD];
    __shared__ float Ws[2][BK][BN + PAD];

    int tid = threadIdx.x;
    int tx = tid & 15;
    int ty = tid >> 4;
    int rowBase = blockIdx.y * BM;
    int colBase = blockIdx.x * BN;

    int ar = tid >> 1;
    int ak = (tid & 1) * 4;
    int wk = tid >> 5;
    int wc = (tid & 31) * 2;

    int aRow = rowBase + ar;
    int wCol = colBase + wc;
    bool aOK = aRow < M;
    bool wOK = wCol < NN;

    ull acc[4][4];
#pragma unroll
    for (int p = 0; p < 4; p++)
#pragma unroll
        for (int j = 0; j < 4; j++) acc[p][j] = 0ull;

    const int ntiles = 2 * K / BK;

    {
        float4 va = make_float4(0.f, 0.f, 0.f, 0.f);
        float2 vw = make_float2(0.f, 0.f);
        if (aOK) va = *(const float4*)(A1 + (size_t)aRow * K + ak);
        if (wOK) vw = *(const float2*)(W1 + (size_t)wk * NN + wCol);
        As[0][ak + 0][ar] = va.x; As[0][ak + 1][ar] = va.y;
        As[0][ak + 2][ar] = va.z; As[0][ak + 3][ar] = va.w;
        *(float2*)&Ws[0][wk][wc] = vw;
    }
    __syncthreads();

    for (int t = 0; t < ntiles; t++) {
        int buf = t & 1;
        bool hasNext = (t + 1) < ntiles;

        float4 na = make_float4(0.f, 0.f, 0.f, 0.f);
        float2 nw = make_float2(0.f, 0.f);
        if (hasNext) {
            int kt = (t + 1) * BK;
            const float* A; const float* W; int ko;
            if (kt < K) { A = A1; W = W1; ko = kt; }
            else        { A = A2; W = W2; ko = kt - K; }
            if (aOK) na = *(const float4*)(A + (size_t)aRow * K + ko + ak);
            if (wOK) nw = *(const float2*)(W + (size_t)(ko + wk) * NN + wCol);
        }

#pragma unroll
        for (int kk = 0; kk < BK; kk++) {
            ulonglong2 la0 = *(const ulonglong2*)&As[buf][kk][ty * 8];
            ulonglong2 la1 = *(const ulonglong2*)&As[buf][kk][ty * 8 + 4];
            ull a2[4] = {la0.x, la0.y, la1.x, la1.y};

            float4 w0 = *(const float4*)&Ws[buf][kk][tx * 4];
            float wv[4] = {w0.x, w0.y, w0.z, w0.w};
            ull w2[4];
#pragma unroll
            for (int j = 0; j < 4; j++) SPLAT_F32X2(w2[j], wv[j]);

#pragma unroll
            for (int p = 0; p < 4; p++)
#pragma unroll
                for (int j = 0; j < 4; j++)
                    FMA_F32X2(acc[p][j], a2[p], w2[j]);
        }

        if (hasNext) {
            int nb = buf ^ 1;
            As[nb][ak + 0][ar] = na.x; As[nb][ak + 1][ar] = na.y;
            As[nb][ak + 2][ar] = na.z; As[nb][ak + 3][ar] = na.w;
            *(float2*)&Ws[nb][wk][wc] = nw;
        }
        __syncthreads();
    }

#pragma unroll
    for (int p = 0; p < 4; p++) {
#pragma unroll
        for (int half = 0; half < 2; half++) {
            int row = rowBase + ty * 8 + p * 2 + half;
            if (row >= M) continue;
#pragma unroll
            for (int j = 0; j < 4; j++) {
                int col = colBase + tx * 4 + j;
                if (col < NN) {
                    float v = half ? f32x2_hi(acc[p][j]) : f32x2_lo(acc[p][j]);
                    out[(size_t)row * NN + col] = v + bias[col];
                }
            }
        }
    }
}

// ---------------- final layer + log_softmax ----------------------------------
__global__ void final_kernel(const float* __restrict__ agg,
                             const float* __restrict__ h,
                             const float* __restrict__ Wl,
                             const float* __restrict__ Wr,
                             const float* __restrict__ b,
                             float* __restrict__ out) {
    __shared__ float sWl[H2 * C_OUT], sWr[H2 * C_OUT], sb[C_OUT];
    for (int i = threadIdx.x; i < H2 * C_OUT; i += blockDim.x) {
        sWl[i] = Wl[i];
        sWr[i] = Wr[i];
    }
    if (threadIdx.x < C_OUT) sb[threadIdx.x] = b[threadIdx.x];
    __syncthreads();

    int n = blockIdx.x * blockDim.x + threadIdx.x;
    if (n >= N_NODES) return;

    float logit[C_OUT];
#pragma unroll
    for (int j = 0; j < C_OUT; j++) logit[j] = sb[j];

    const float* ar = agg + (size_t)n * H2;
    const float* hr = h   + (size_t)n * H2;
#pragma unroll 5
    for (int k = 0; k < H2; k++) {
        float a  = ar[k];
        float hh = hr[k];
#pragma unroll
        for (int j = 0; j < C_OUT; j++)
            logit[j] += a * sWl[k * C_OUT + j] + hh * sWr[k * C_OUT + j];
    }

    float mx = logit[0];
#pragma unroll
    for (int j = 1; j < C_OUT; j++) mx = fmaxf(mx, logit[j]);
    float s = 0.0f;
#pragma unroll
    for (int j = 0; j < C_OUT; j++) s += expf(logit[j] - mx);
    float lse = mx + logf(s);
#pragma unroll
    for (int j = 0; j < C_OUT; j++) out[(size_t)n * C_OUT + j] = logit[j] - lse;
}

// ---------------- launch ------------------------------------------------------
extern "C" void kernel_launch(void* const* d_in, const int* in_sizes, int n_in,
                              void* d_out, int out_size) {
    const float* x    = (const float*)d_in[0];
    const int*   ei   = (const int*)d_in[1];
    const float* W_l1 = (const float*)d_in[2];
    const float* b1   = (const float*)d_in[3];
    const float* W_r1 = (const float*)d_in[4];
    const float* W_l2 = (const float*)d_in[5];
    const float* b2   = (const float*)d_in[6];
    const float* W_r2 = (const float*)d_in[7];
    const float* W_l3 = (const float*)d_in[8];
    const float* b3   = (const float*)d_in[9];
    const float* W_r3 = (const float*)d_in[10];
    float* out = (float*)d_out;

    const int* src = ei;
    const int* dst = ei + N_EDGES;

    float *agg1, *h1, *agg2, *h2, *agg3;
    cudaGetSymbolAddress((void**)&agg1, g_agg1);
    cudaGetSymbolAddress((void**)&h1,   g_h1);
    cudaGetSymbolAddress((void**)&agg2, g_agg2);
    cudaGetSymbolAddress((void**)&h2,   g_h2);
    cudaGetSymbolAddress((void**)&agg3, g_agg3);

    zero_cnt_kernel<<<(N_NODES + 255) / 256, 256>>>();
    bucket_build_kernel<<<(N_EDGES + 255) / 256, 256>>>(src, dst);

    const int aggBlocks = (N_NODES * 32 + 255) / 256;

    // layer 1
    agg_kernel<F_IN><<<aggBlocks, 256>>>(x, agg1);
    {
        dim3 grid((H1 + 127) / 128, (N_NODES + 127) / 128);
        gemm128_dual<<<grid, 256>>>(agg1, x, W_l1, W_r1, b1, h1,
                                    N_NODES, F_IN, H1);
    }

    // layer 2
    agg_kernel<H1><<<aggBlocks, 256>>>(h1, agg2);
    {
        dim3 grid((H2 + 63) / 64, (N_NODES + 127) / 128);
        gemm64_dual<<<grid, 256>>>(agg2, h1, W_l2, W_r2, b2, h2,
                                   N_NODES, H1, H2);
    }

    // layer 3 + log_softmax
    agg_kernel<H2><<<aggBlocks, 256>>>(h2, agg3);
    final_kernel<<<(N_NODES + 255) / 256, 256>>>(agg3, h2, W_l3, W_r3, b3, out);
}

// round 5
// speedup vs baseline: 1.1294x; 1.1294x over previous
#include <cuda_runtime.h>
#include <cuda_bf16.h>
#include <math.h>

#define N_NODES 100000
#define N_EDGES 1600000
#define F_IN   128
#define H1     200
#define H2     50
#define C_OUT  10
#define MAXDEG 128

// ---------------- scratch -----------------------------------------------------
__device__ int   g_cnt[N_NODES];
__device__ int   g_bucket[(size_t)N_NODES * MAXDEG];
__device__ float g_agg1[(size_t)N_NODES * F_IN];
__device__ float g_h1  [(size_t)N_NODES * H1];
__device__ float g_agg2[(size_t)N_NODES * H1];
__device__ float g_h2  [(size_t)N_NODES * H2];
__device__ float g_agg3[(size_t)N_NODES * H2];

// ---------------- bucket build ------------------------------------------------
__global__ void zero_cnt_kernel() {
    int i = blockIdx.x * blockDim.x + threadIdx.x;
    if (i < N_NODES) g_cnt[i] = 0;
}

__global__ void bucket_build_kernel(const int* __restrict__ src,
                                    const int* __restrict__ dst) {
    int e = blockIdx.x * blockDim.x + threadIdx.x;
    if (e >= N_EDGES) return;
    int d = dst[e];
    int p = atomicAdd(&g_cnt[d], 1);
    if (p < MAXDEG) g_bucket[(size_t)d * MAXDEG + p] = src[e];
}

// ---------------- aggregation: warp/node, float2 gather, 4-edge MLP ----------
template <int F>
__global__ void agg_kernel(const float* __restrict__ x, float* __restrict__ agg) {
    constexpr int C2 = F / 2;
    constexpr int RV = (C2 + 31) / 32;

    int gwarp = (blockIdx.x * blockDim.x + threadIdx.x) >> 5;
    int lane  = threadIdx.x & 31;
    if (gwarp >= N_NODES) return;

    int c = g_cnt[gwarp];
    if (c > MAXDEG) c = MAXDEG;

    float2 m[RV];
#pragma unroll
    for (int r = 0; r < RV; r++) { m[r].x = -INFINITY; m[r].y = -INFINITY; }

    const int* bk = g_bucket + (size_t)gwarp * MAXDEG;
    int i = 0;
    for (; i + 3 < c; i += 4) {
        int s0 = bk[i], s1 = bk[i + 1], s2 = bk[i + 2], s3 = bk[i + 3];
        const float2* r0 = (const float2*)(x + (size_t)s0 * F);
        const float2* r1 = (const float2*)(x + (size_t)s1 * F);
        const float2* r2 = (const float2*)(x + (size_t)s2 * F);
        const float2* r3 = (const float2*)(x + (size_t)s3 * F);
#pragma unroll
        for (int r = 0; r < RV; r++) {
            int ch = lane + r * 32;
            if (ch < C2) {
                float2 v0 = r0[ch], v1 = r1[ch], v2 = r2[ch], v3 = r3[ch];
                m[r].x = fmaxf(m[r].x, fmaxf(fmaxf(v0.x, v1.x), fmaxf(v2.x, v3.x)));
                m[r].y = fmaxf(m[r].y, fmaxf(fmaxf(v0.y, v1.y), fmaxf(v2.y, v3.y)));
            }
        }
    }
    for (; i < c; i++) {
        const float2* r0 = (const float2*)(x + (size_t)bk[i] * F);
#pragma unroll
        for (int r = 0; r < RV; r++) {
            int ch = lane + r * 32;
            if (ch < C2) {
                float2 v0 = r0[ch];
                m[r].x = fmaxf(m[r].x, v0.x);
                m[r].y = fmaxf(m[r].y, v0.y);
            }
        }
    }

    float2* out = (float2*)(agg + (size_t)gwarp * F);
#pragma unroll
    for (int r = 0; r < RV; r++) {
        int ch = lane + r * 32;
        if (ch < C2) out[ch] = (c == 0) ? make_float2(0.f, 0.f) : m[r];
    }
}

// ---------------- bf16-split tensor-core dual GEMM --------------------------
// out[M,NN] = A1@W1 + A2@W2 + bias using mma.sync m16n8k16 bf16 with
// hi/lo splitting (hi*hi + hi*lo + lo*hi) for near-fp32 accuracy.

#define MMA16816(d, a, b0, b1)                                                \
    asm volatile(                                                             \
        "mma.sync.aligned.m16n8k16.row.col.f32.bf16.bf16.f32 "                \
        "{%0,%1,%2,%3}, {%4,%5,%6,%7}, {%8,%9}, {%0,%1,%2,%3};"               \
        : "+f"(d[0]), "+f"(d[1]), "+f"(d[2]), "+f"(d[3])                      \
        : "r"(a[0]), "r"(a[1]), "r"(a[2]), "r"(a[3]), "r"(b0), "r"(b1))

__device__ __forceinline__ void bf16_split(float x, __nv_bfloat16& h,
                                           __nv_bfloat16& l) {
    h = __float2bfloat16(x);
    l = __float2bfloat16(x - __bfloat162float(h));
}

// WM x WN warp grid (256 threads = 8 warps, WM*WN == 8). Each warp computes
// 32 rows x NT*8 cols. BK = 16. LDS stride 24 bf16 (48B) -> conflict-free
// fragment loads (bank = 12*g + t, all distinct within a phase).
template <int WM, int WN, int NT, int LOGBN>
__global__ __launch_bounds__(256, 2)
void gemm_mma_dual(const float* __restrict__ A1, const float* __restrict__ A2,
                   const float* __restrict__ W1, const float* __restrict__ W2,
                   const float* __restrict__ bias, float* __restrict__ out,
                   int M, int K, int NN) {
    constexpr int BM = WM * 32;
    constexpr int BN = WN * NT * 8;
    constexpr int LDSTR = 24;   // bf16 elems per smem row (16 data + 8 pad)

    __shared__ __align__(16) __nv_bfloat16 Ash[BM * LDSTR];
    __shared__ __align__(16) __nv_bfloat16 Asl[BM * LDSTR];
    __shared__ __align__(16) __nv_bfloat16 Bsh[BN * LDSTR];
    __shared__ __align__(16) __nv_bfloat16 Bsl[BN * LDSTR];

    int tid = threadIdx.x;
    int lane = tid & 31;
    int wid = tid >> 5;
    int wm = wid % WM;
    int wn = wid / WM;
    int g  = lane >> 2;       // group id (rows/cols within fragment)
    int tg = lane & 3;        // thread-in-group (k pairs)

    int rowBase = blockIdx.y * BM;
    int colBase = blockIdx.x * BN;

    float acc[2][NT][4];
#pragma unroll
    for (int mt = 0; mt < 2; mt++)
#pragma unroll
        for (int nt = 0; nt < NT; nt++)
#pragma unroll
            for (int c = 0; c < 4; c++) acc[mt][nt][c] = 0.f;

#pragma unroll 1
    for (int phase = 0; phase < 2; phase++) {
        const float* A = phase ? A2 : A1;
        const float* W = phase ? W2 : W1;
        int ntiles = (K + 15) >> 4;

#pragma unroll 1
        for (int t = 0; t < ntiles; t++) {
            int ko = t << 4;

            // ---- load A tile: BM x 16 fp32, one float4 quad per unit ----
            for (int u = tid; u < BM * 4; u += 256) {
                int r  = u >> 2;
                int kq = (u & 3) << 2;
                int grow = rowBase + r;
                int gk = ko + kq;
                float v[4] = {0.f, 0.f, 0.f, 0.f};
                if (grow < M) {
                    if (gk + 3 < K) {
                        float4 f = *(const float4*)(A + (size_t)grow * K + gk);
                        v[0] = f.x; v[1] = f.y; v[2] = f.z; v[3] = f.w;
                    } else {
#pragma unroll
                        for (int i = 0; i < 4; i++)
                            if (gk + i < K) v[i] = A[(size_t)grow * K + gk + i];
                    }
                }
                __nv_bfloat16 h[4], l[4];
#pragma unroll
                for (int i = 0; i < 4; i++) bf16_split(v[i], h[i], l[i]);
                *(__nv_bfloat162*)&Ash[r * LDSTR + kq]     = *(__nv_bfloat162*)&h[0];
                *(__nv_bfloat162*)&Ash[r * LDSTR + kq + 2] = *(__nv_bfloat162*)&h[2];
                *(__nv_bfloat162*)&Asl[r * LDSTR + kq]     = *(__nv_bfloat162*)&l[0];
                *(__nv_bfloat162*)&Asl[r * LDSTR + kq + 2] = *(__nv_bfloat162*)&l[2];
            }

            // ---- load B tile (W^T): 16 x BN fp32, k-column per unit ----
            for (int u = tid; u < 4 * BN; u += 256) {
                int n  = u & (BN - 1);
                int kq = (u >> LOGBN) << 2;
                int gn = colBase + n;
                float v[4] = {0.f, 0.f, 0.f, 0.f};
                if (gn < NN) {
#pragma unroll
                    for (int i = 0; i < 4; i++) {
                        int gk = ko + kq + i;
                        if (gk < K) v[i] = W[(size_t)gk * NN + gn];
                    }
                }
                __nv_bfloat16 h[4], l[4];
#pragma unroll
                for (int i = 0; i < 4; i++) bf16_split(v[i], h[i], l[i]);
                *(__nv_bfloat162*)&Bsh[n * LDSTR + kq]     = *(__nv_bfloat162*)&h[0];
                *(__nv_bfloat162*)&Bsh[n * LDSTR + kq + 2] = *(__nv_bfloat162*)&h[2];
                *(__nv_bfloat162*)&Bsl[n * LDSTR + kq]     = *(__nv_bfloat162*)&l[0];
                *(__nv_bfloat162*)&Bsl[n * LDSTR + kq + 2] = *(__nv_bfloat162*)&l[2];
            }
            __syncthreads();

            // ---- A fragments (hi & lo), 2 m16 tiles per warp ----
            unsigned afh[2][4], afl[2][4];
#pragma unroll
            for (int mt = 0; mt < 2; mt++) {
                int r0 = wm * 32 + mt * 16 + g;
                afh[mt][0] = *(const unsigned*)&Ash[(r0)     * LDSTR + 2 * tg];
                afh[mt][1] = *(const unsigned*)&Ash[(r0 + 8) * LDSTR + 2 * tg];
                afh[mt][2] = *(const unsigned*)&Ash[(r0)     * LDSTR + 2 * tg + 8];
                afh[mt][3] = *(const unsigned*)&Ash[(r0 + 8) * LDSTR + 2 * tg + 8];
                afl[mt][0] = *(const unsigned*)&Asl[(r0)     * LDSTR + 2 * tg];
                afl[mt][1] = *(const unsigned*)&Asl[(r0 + 8) * LDSTR + 2 * tg];
                afl[mt][2] = *(const unsigned*)&Asl[(r0)     * LDSTR + 2 * tg + 8];
                afl[mt][3] = *(const unsigned*)&Asl[(r0 + 8) * LDSTR + 2 * tg + 8];
            }

#pragma unroll
            for (int nt = 0; nt < NT; nt++) {
                int c0 = (wn * NT + nt) * 8 + g;
                unsigned bh0 = *(const unsigned*)&Bsh[c0 * LDSTR + 2 * tg];
                unsigned bh1 = *(const unsigned*)&Bsh[c0 * LDSTR + 2 * tg + 8];
                unsigned bl0 = *(const unsigned*)&Bsl[c0 * LDSTR + 2 * tg];
                unsigned bl1 = *(const unsigned*)&Bsl[c0 * LDSTR + 2 * tg + 8];
#pragma unroll
                for (int mt = 0; mt < 2; mt++) {
                    MMA16816(acc[mt][nt], afh[mt], bh0, bh1);
                    MMA16816(acc[mt][nt], afh[mt], bl0, bl1);
                    MMA16816(acc[mt][nt], afl[mt], bh0, bh1);
                }
            }
            __syncthreads();
        }
    }

    // ---- epilogue: add bias, store fp32 ----
#pragma unroll
    for (int mt = 0; mt < 2; mt++) {
#pragma unroll
        for (int nt = 0; nt < NT; nt++) {
            int col = colBase + (wn * NT + nt) * 8 + 2 * tg;
            if (col >= NN) continue;
            float2 bv = *(const float2*)(bias + col);
            int row0 = rowBase + wm * 32 + mt * 16 + g;
            if (row0 < M) {
                float2 o = make_float2(acc[mt][nt][0] + bv.x,
                                       acc[mt][nt][1] + bv.y);
                *(float2*)(out + (size_t)row0 * NN + col) = o;
            }
            int row1 = row0 + 8;
            if (row1 < M) {
                float2 o = make_float2(acc[mt][nt][2] + bv.x,
                                       acc[mt][nt][3] + bv.y);
                *(float2*)(out + (size_t)row1 * NN + col) = o;
            }
        }
    }
}

// ---------------- final layer + log_softmax ----------------------------------
__global__ void final_kernel(const float* __restrict__ agg,
                             const float* __restrict__ h,
                             const float* __restrict__ Wl,
                             const float* __restrict__ Wr,
                             const float* __restrict__ b,
                             float* __restrict__ out) {
    __shared__ float sWl[H2 * C_OUT], sWr[H2 * C_OUT], sb[C_OUT];
    for (int i = threadIdx.x; i < H2 * C_OUT; i += blockDim.x) {
        sWl[i] = Wl[i];
        sWr[i] = Wr[i];
    }
    if (threadIdx.x < C_OUT) sb[threadIdx.x] = b[threadIdx.x];
    __syncthreads();

    int n = blockIdx.x * blockDim.x + threadIdx.x;
    if (n >= N_NODES) return;

    float logit[C_OUT];
#pragma unroll
    for (int j = 0; j < C_OUT; j++) logit[j] = sb[j];

    const float* ar = agg + (size_t)n * H2;
    const float* hr = h   + (size_t)n * H2;
#pragma unroll 5
    for (int k = 0; k < H2; k++) {
        float a  = ar[k];
        float hh = hr[k];
#pragma unroll
        for (int j = 0; j < C_OUT; j++)
            logit[j] += a * sWl[k * C_OUT + j] + hh * sWr[k * C_OUT + j];
    }

    float mx = logit[0];
#pragma unroll
    for (int j = 1; j < C_OUT; j++) mx = fmaxf(mx, logit[j]);
    float s = 0.0f;
#pragma unroll
    for (int j = 0; j < C_OUT; j++) s += expf(logit[j] - mx);
    float lse = mx + logf(s);
#pragma unroll
    for (int j = 0; j < C_OUT; j++) out[(size_t)n * C_OUT + j] = logit[j] - lse;
}

// ---------------- launch ------------------------------------------------------
extern "C" void kernel_launch(void* const* d_in, const int* in_sizes, int n_in,
                              void* d_out, int out_size) {
    const float* x    = (const float*)d_in[0];
    const int*   ei   = (const int*)d_in[1];
    const float* W_l1 = (const float*)d_in[2];
    const float* b1   = (const float*)d_in[3];
    const float* W_r1 = (const float*)d_in[4];
    const float* W_l2 = (const float*)d_in[5];
    const float* b2   = (const float*)d_in[6];
    const float* W_r2 = (const float*)d_in[7];
    const float* W_l3 = (const float*)d_in[8];
    const float* b3   = (const float*)d_in[9];
    const float* W_r3 = (const float*)d_in[10];
    float* out = (float*)d_out;

    const int* src = ei;
    const int* dst = ei + N_EDGES;

    float *agg1, *h1, *agg2, *h2, *agg3;
    cudaGetSymbolAddress((void**)&agg1, g_agg1);
    cudaGetSymbolAddress((void**)&h1,   g_h1);
    cudaGetSymbolAddress((void**)&agg2, g_agg2);
    cudaGetSymbolAddress((void**)&h2,   g_h2);
    cudaGetSymbolAddress((void**)&agg3, g_agg3);

    zero_cnt_kernel<<<(N_NODES + 255) / 256, 256>>>();
    bucket_build_kernel<<<(N_EDGES + 255) / 256, 256>>>(src, dst);

    const int aggBlocks = (N_NODES * 32 + 255) / 256;

    // layer 1: BM=128 (WM=4), BN=128 (WN=2, NT=8, LOGBN=7)
    agg_kernel<F_IN><<<aggBlocks, 256>>>(x, agg1);
    {
        dim3 grid((H1 + 127) / 128, (N_NODES + 127) / 128);
        gemm_mma_dual<4, 2, 8, 7><<<grid, 256>>>(agg1, x, W_l1, W_r1, b1, h1,
                                                 N_NODES, F_IN, H1);
    }

    // layer 2: BM=256 (WM=8), BN=64 (WN=1, NT=8, LOGBN=6)
    agg_kernel<H1><<<aggBlocks, 256>>>(h1, agg2);
    {
        dim3 grid(1, (N_NODES + 255) / 256);
        gemm_mma_dual<8, 1, 8, 6><<<grid, 256>>>(agg2, h1, W_l2, W_r2, b2, h2,
                                                 N_NODES, H1, H2);
    }

    // layer 3 + log_softmax
    agg_kernel<H2><<<aggBlocks, 256>>>(h2, agg3);
    final_kernel<<<(N_NODES + 255) / 256, 256>>>(agg3, h2, W_l3, W_r3, b3, out);
}

// round 6
// speedup vs baseline: 1.3377x; 1.1844x over previous
#include <cuda_runtime.h>
#include <cuda_bf16.h>
#include <math.h>

#define N_NODES 100000
#define N_EDGES 1600000
#define F_IN   128
#define H1     200
#define H2     50
#define C_OUT  10
#define MAXDEG 128

// ---------------- scratch -----------------------------------------------------
__device__ int   g_cnt[N_NODES];
__device__ int   g_bucket[(size_t)N_NODES * MAXDEG];
__device__ __nv_bfloat16 g_xh  [(size_t)N_NODES * F_IN];
__device__ __nv_bfloat16 g_xl  [(size_t)N_NODES * F_IN];
__device__ __nv_bfloat16 g_a1h [(size_t)N_NODES * F_IN];
__device__ __nv_bfloat16 g_a1l [(size_t)N_NODES * F_IN];
__device__ __nv_bfloat16 g_h1h [(size_t)N_NODES * H1];
__device__ __nv_bfloat16 g_h1l [(size_t)N_NODES * H1];
__device__ __nv_bfloat16 g_a2h [(size_t)N_NODES * H1];
__device__ __nv_bfloat16 g_a2l [(size_t)N_NODES * H1];
__device__ float g_h2  [(size_t)N_NODES * H2];
__device__ float g_agg3[(size_t)N_NODES * H2];

__device__ __forceinline__ void bf16_split(float x, __nv_bfloat16& h,
                                           __nv_bfloat16& l) {
    h = __float2bfloat16(x);
    l = __float2bfloat16(x - __bfloat162float(h));
}

__device__ __forceinline__ unsigned pack2(__nv_bfloat16 a, __nv_bfloat16 b) {
    __nv_bfloat162 p = __halves2bfloat162(a, b);
    return *reinterpret_cast<unsigned*>(&p);
}

// ---------------- bucket build ------------------------------------------------
__global__ void zero_cnt_kernel() {
    int i = blockIdx.x * blockDim.x + threadIdx.x;
    if (i < N_NODES) g_cnt[i] = 0;
}

__global__ void bucket_build_kernel(const int* __restrict__ src,
                                    const int* __restrict__ dst) {
    int e = blockIdx.x * blockDim.x + threadIdx.x;
    if (e >= N_EDGES) return;
    int d = dst[e];
    int p = atomicAdd(&g_cnt[d], 1);
    if (p < MAXDEG) g_bucket[(size_t)d * MAXDEG + p] = src[e];
}

// ---------------- one-time split of x ----------------------------------------
__global__ void split_x_kernel(const float* __restrict__ x,
                               __nv_bfloat16* __restrict__ xh,
                               __nv_bfloat16* __restrict__ xl) {
    int i = blockIdx.x * blockDim.x + threadIdx.x;
    if (i >= N_NODES * F_IN / 4) return;
    float4 v = ((const float4*)x)[i];
    __nv_bfloat16 h[4], l[4];
    bf16_split(v.x, h[0], l[0]);
    bf16_split(v.y, h[1], l[1]);
    bf16_split(v.z, h[2], l[2]);
    bf16_split(v.w, h[3], l[3]);
    uint2 uh, ul;
    uh.x = pack2(h[0], h[1]); uh.y = pack2(h[2], h[3]);
    ul.x = pack2(l[0], l[1]); ul.y = pack2(l[2], l[3]);
    *(uint2*)(xh + (size_t)i * 4) = uh;
    *(uint2*)(xl + (size_t)i * 4) = ul;
}

// ---------------- aggregation over hi/lo bf16 --------------------------------
__device__ __forceinline__ void max4_from(float m[4], uint2 h, uint2 l) {
    float2 fa = __bfloat1622float2(*reinterpret_cast<__nv_bfloat162*>(&h.x));
    float2 fb = __bfloat1622float2(*reinterpret_cast<__nv_bfloat162*>(&h.y));
    float2 ga = __bfloat1622float2(*reinterpret_cast<__nv_bfloat162*>(&l.x));
    float2 gb = __bfloat1622float2(*reinterpret_cast<__nv_bfloat162*>(&l.y));
    m[0] = fmaxf(m[0], fa.x + ga.x);
    m[1] = fmaxf(m[1], fa.y + ga.y);
    m[2] = fmaxf(m[2], fb.x + gb.x);
    m[3] = fmaxf(m[3], fb.y + gb.y);
}

template <int F>
__global__ void agg_bf16_kernel(const __nv_bfloat16* __restrict__ xh,
                                const __nv_bfloat16* __restrict__ xl,
                                __nv_bfloat16* __restrict__ oh,
                                __nv_bfloat16* __restrict__ ol) {
    constexpr int C4 = F / 4;
    constexpr int RV = (C4 + 31) / 32;

    int gwarp = (blockIdx.x * blockDim.x + threadIdx.x) >> 5;
    int lane  = threadIdx.x & 31;
    if (gwarp >= N_NODES) return;

    int c = g_cnt[gwarp];
    if (c > MAXDEG) c = MAXDEG;

    float m[RV][4];
#pragma unroll
    for (int r = 0; r < RV; r++)
#pragma unroll
        for (int q = 0; q < 4; q++) m[r][q] = -INFINITY;

    const int* bk = g_bucket + (size_t)gwarp * MAXDEG;
    int i = 0;
    for (; i + 3 < c; i += 4) {
        int s0 = bk[i], s1 = bk[i + 1], s2 = bk[i + 2], s3 = bk[i + 3];
#pragma unroll
        for (int r = 0; r < RV; r++) {
            int ch = lane + r * 32;
            if (ch < C4) {
                size_t o0 = (size_t)s0 * F + ch * 4;
                size_t o1 = (size_t)s1 * F + ch * 4;
                size_t o2 = (size_t)s2 * F + ch * 4;
                size_t o3 = (size_t)s3 * F + ch * 4;
                uint2 h0 = *(const uint2*)(xh + o0), l0 = *(const uint2*)(xl + o0);
                uint2 h1 = *(const uint2*)(xh + o1), l1 = *(const uint2*)(xl + o1);
                uint2 h2v = *(const uint2*)(xh + o2), l2 = *(const uint2*)(xl + o2);
                uint2 h3 = *(const uint2*)(xh + o3), l3 = *(const uint2*)(xl + o3);
                max4_from(m[r], h0, l0);
                max4_from(m[r], h1, l1);
                max4_from(m[r], h2v, l2);
                max4_from(m[r], h3, l3);
            }
        }
    }
    for (; i < c; i++) {
        int s0 = bk[i];
#pragma unroll
        for (int r = 0; r < RV; r++) {
            int ch = lane + r * 32;
            if (ch < C4) {
                size_t o0 = (size_t)s0 * F + ch * 4;
                uint2 h0 = *(const uint2*)(xh + o0), l0 = *(const uint2*)(xl + o0);
                max4_from(m[r], h0, l0);
            }
        }
    }

#pragma unroll
    for (int r = 0; r < RV; r++) {
        int ch = lane + r * 32;
        if (ch < C4) {
            __nv_bfloat16 hh[4], ll[4];
#pragma unroll
            for (int q = 0; q < 4; q++) {
                float v = (c == 0) ? 0.f : m[r][q];
                bf16_split(v, hh[q], ll[q]);
            }
            uint2 uh, ul;
            uh.x = pack2(hh[0], hh[1]); uh.y = pack2(hh[2], hh[3]);
            ul.x = pack2(ll[0], ll[1]); ul.y = pack2(ll[2], ll[3]);
            *(uint2*)(oh + (size_t)gwarp * F + ch * 4) = uh;
            *(uint2*)(ol + (size_t)gwarp * F + ch * 4) = ul;
        }
    }
}

// ---------------- fp32 aggregation (layer 3, H2=50) --------------------------
template <int F>
__global__ void agg_kernel(const float* __restrict__ x, float* __restrict__ agg) {
    constexpr int C2 = F / 2;
    constexpr int RV = (C2 + 31) / 32;

    int gwarp = (blockIdx.x * blockDim.x + threadIdx.x) >> 5;
    int lane  = threadIdx.x & 31;
    if (gwarp >= N_NODES) return;

    int c = g_cnt[gwarp];
    if (c > MAXDEG) c = MAXDEG;

    float2 m[RV];
#pragma unroll
    for (int r = 0; r < RV; r++) { m[r].x = -INFINITY; m[r].y = -INFINITY; }

    const int* bk = g_bucket + (size_t)gwarp * MAXDEG;
    int i = 0;
    for (; i + 3 < c; i += 4) {
        int s0 = bk[i], s1 = bk[i + 1], s2 = bk[i + 2], s3 = bk[i + 3];
        const float2* r0 = (const float2*)(x + (size_t)s0 * F);
        const float2* r1 = (const float2*)(x + (size_t)s1 * F);
        const float2* r2 = (const float2*)(x + (size_t)s2 * F);
        const float2* r3 = (const float2*)(x + (size_t)s3 * F);
#pragma unroll
        for (int r = 0; r < RV; r++) {
            int ch = lane + r * 32;
            if (ch < C2) {
                float2 v0 = r0[ch], v1 = r1[ch], v2 = r2[ch], v3 = r3[ch];
                m[r].x = fmaxf(m[r].x, fmaxf(fmaxf(v0.x, v1.x), fmaxf(v2.x, v3.x)));
                m[r].y = fmaxf(m[r].y, fmaxf(fmaxf(v0.y, v1.y), fmaxf(v2.y, v3.y)));
            }
        }
    }
    for (; i < c; i++) {
        const float2* r0 = (const float2*)(x + (size_t)bk[i] * F);
#pragma unroll
        for (int r = 0; r < RV; r++) {
            int ch = lane + r * 32;
            if (ch < C2) {
                float2 v0 = r0[ch];
                m[r].x = fmaxf(m[r].x, v0.x);
                m[r].y = fmaxf(m[r].y, v0.y);
            }
        }
    }

    float2* out = (float2*)(agg + (size_t)gwarp * F);
#pragma unroll
    for (int r = 0; r < RV; r++) {
        int ch = lane + r * 32;
        if (ch < C2) out[ch] = (c == 0) ? make_float2(0.f, 0.f) : m[r];
    }
}

// ---------------- pre-split bf16 tensor-core dual GEMM -----------------------
#define MMA16816(d, a, b0, b1)                                                \
    asm volatile(                                                             \
        "mma.sync.aligned.m16n8k16.row.col.f32.bf16.bf16.f32 "                \
        "{%0,%1,%2,%3}, {%4,%5,%6,%7}, {%8,%9}, {%0,%1,%2,%3};"               \
        : "+f"(d[0]), "+f"(d[1]), "+f"(d[2]), "+f"(d[3])                      \
        : "r"(a[0]), "r"(a[1]), "r"(a[2]), "r"(a[3]), "r"(b0), "r"(b1))

// WM=4 fixed (BM=128). 256 threads, 8 warps (4 x WN). Double-buffered smem,
// one sync per 16-k tile. A arrives pre-split bf16; W converted in-kernel.
template <int WN, int NT, int LOGBN, bool SPLIT_OUT>
__global__ __launch_bounds__(256, 2)
void gemm_mma_ps(const __nv_bfloat16* __restrict__ Ah1,
                 const __nv_bfloat16* __restrict__ Al1,
                 const __nv_bfloat16* __restrict__ Ah2,
                 const __nv_bfloat16* __restrict__ Al2,
                 const float* __restrict__ W1, const float* __restrict__ W2,
                 const float* __restrict__ bias,
                 float* __restrict__ outf,
                 __nv_bfloat16* __restrict__ outh,
                 __nv_bfloat16* __restrict__ outl,
                 int M, int K, int NN) {
    constexpr int WM = 4;
    constexpr int BM = 128;
    constexpr int BN = WN * NT * 8;
    constexpr int LDSTR = 24;            // conflict-free fragment loads
    constexpr int BU = (4 * BN) / 256;   // B load units per thread

    __shared__ __align__(16) __nv_bfloat16 Ash[2][BM * LDSTR];
    __shared__ __align__(16) __nv_bfloat16 Asl[2][BM * LDSTR];
    __shared__ __align__(16) __nv_bfloat16 Bsh[2][BN * LDSTR];
    __shared__ __align__(16) __nv_bfloat16 Bsl[2][BN * LDSTR];

    int tid = threadIdx.x;
    int lane = tid & 31;
    int wid = tid >> 5;
    int wm = wid % WM;
    int wn = wid / WM;
    int g  = lane >> 2;
    int tg = lane & 3;

    int rowBase = blockIdx.y * BM;
    int colBase = blockIdx.x * BN;

    int npt  = (K + 15) >> 4;
    int totT = 2 * npt;

    // fixed per-thread load coordinates
    const int r_  = tid >> 1;
    const int kh_ = (tid & 1) * 8;
    const int aRow = rowBase + r_;

    float acc[2][NT][4];
#pragma unroll
    for (int mt = 0; mt < 2; mt++)
#pragma unroll
        for (int nt = 0; nt < NT; nt++)
#pragma unroll
            for (int q = 0; q < 4; q++) acc[mt][nt][q] = 0.f;

    uint4 pAh, pAl;
    float pB[BU][4];

    auto prefetch = [&](int t) {
        const __nv_bfloat16 *Ah, *Al; const float* W; int ko;
        if (t < npt) { Ah = Ah1; Al = Al1; W = W1; ko = t << 4; }
        else         { Ah = Ah2; Al = Al2; W = W2; ko = (t - npt) << 4; }

        int gk = ko + kh_;
        pAh = make_uint4(0u, 0u, 0u, 0u);
        pAl = make_uint4(0u, 0u, 0u, 0u);
        if (aRow < M && gk + 8 <= K) {   // K%8==0 -> chunk all-valid or all-out
            pAh = *(const uint4*)(Ah + (size_t)aRow * K + gk);
            pAl = *(const uint4*)(Al + (size_t)aRow * K + gk);
        }
#pragma unroll
        for (int bu = 0; bu < BU; bu++) {
            int u = tid + bu * 256;
            int n = u & (BN - 1);
            int kq = (u >> LOGBN) << 2;
            int gn = colBase + n;
#pragma unroll
            for (int q = 0; q < 4; q++) {
                int gk2 = ko + kq + q;
                pB[bu][q] = (gn < NN && gk2 < K) ? W[(size_t)gk2 * NN + gn] : 0.f;
            }
        }
    };

    auto sts = [&](int buf) {
        *(uint4*)&Ash[buf][r_ * LDSTR + kh_] = pAh;
        *(uint4*)&Asl[buf][r_ * LDSTR + kh_] = pAl;
#pragma unroll
        for (int bu = 0; bu < BU; bu++) {
            int u = tid + bu * 256;
            int n = u & (BN - 1);
            int kq = (u >> LOGBN) << 2;
            __nv_bfloat16 h[4], l[4];
#pragma unroll
            for (int q = 0; q < 4; q++) bf16_split(pB[bu][q], h[q], l[q]);
            uint2 uh, ul;
            uh.x = pack2(h[0], h[1]); uh.y = pack2(h[2], h[3]);
            ul.x = pack2(l[0], l[1]); ul.y = pack2(l[2], l[3]);
            *(uint2*)&Bsh[buf][n * LDSTR + kq] = uh;
            *(uint2*)&Bsl[buf][n * LDSTR + kq] = ul;
        }
    };

    auto compute = [&](int buf) {
        unsigned afh[2][4], afl[2][4];
#pragma unroll
        for (int mt = 0; mt < 2; mt++) {
            int r0 = wm * 32 + mt * 16 + g;
            afh[mt][0] = *(const unsigned*)&Ash[buf][(r0)     * LDSTR + 2 * tg];
            afh[mt][1] = *(const unsigned*)&Ash[buf][(r0 + 8) * LDSTR + 2 * tg];
            afh[mt][2] = *(const unsigned*)&Ash[buf][(r0)     * LDSTR + 2 * tg + 8];
            afh[mt][3] = *(const unsigned*)&Ash[buf][(r0 + 8) * LDSTR + 2 * tg + 8];
            afl[mt][0] = *(const unsigned*)&Asl[buf][(r0)     * LDSTR + 2 * tg];
            afl[mt][1] = *(const unsigned*)&Asl[buf][(r0 + 8) * LDSTR + 2 * tg];
            afl[mt][2] = *(const unsigned*)&Asl[buf][(r0)     * LDSTR + 2 * tg + 8];
            afl[mt][3] = *(const unsigned*)&Asl[buf][(r0 + 8) * LDSTR + 2 * tg + 8];
        }
#pragma unroll
        for (int nt = 0; nt < NT; nt++) {
            int c0 = (wn * NT + nt) * 8 + g;
            unsigned bh0 = *(const unsigned*)&Bsh[buf][c0 * LDSTR + 2 * tg];
            unsigned bh1 = *(const unsigned*)&Bsh[buf][c0 * LDSTR + 2 * tg + 8];
            unsigned bl0 = *(const unsigned*)&Bsl[buf][c0 * LDSTR + 2 * tg];
            unsigned bl1 = *(const unsigned*)&Bsl[buf][c0 * LDSTR + 2 * tg + 8];
#pragma unroll
            for (int mt = 0; mt < 2; mt++) {
                MMA16816(acc[mt][nt], afh[mt], bh0, bh1);
                MMA16816(acc[mt][nt], afh[mt], bl0, bl1);
                MMA16816(acc[mt][nt], afl[mt], bh0, bh1);
            }
        }
    };

    prefetch(0);
    sts(0);
    __syncthreads();

    for (int t = 0; t < totT; t++) {
        int buf = t & 1;
        if (t + 1 < totT) prefetch(t + 1);
        compute(buf);
        if (t + 1 < totT) sts(buf ^ 1);
        __syncthreads();
    }

    // ---- epilogue ----
#pragma unroll
    for (int mt = 0; mt < 2; mt++) {
#pragma unroll
        for (int nt = 0; nt < NT; nt++) {
            int col = colBase + (wn * NT + nt) * 8 + 2 * tg;
            if (col >= NN) continue;
            float2 bv = *(const float2*)(bias + col);
            int row0 = rowBase + wm * 32 + mt * 16 + g;
            int row1 = row0 + 8;
            float v0x = acc[mt][nt][0] + bv.x, v0y = acc[mt][nt][1] + bv.y;
            float v1x = acc[mt][nt][2] + bv.x, v1y = acc[mt][nt][3] + bv.y;
            if (SPLIT_OUT) {
                if (row0 < M) {
                    __nv_bfloat16 hx, lx, hy, ly;
                    bf16_split(v0x, hx, lx); bf16_split(v0y, hy, ly);
                    unsigned uh = pack2(hx, hy), ul = pack2(lx, ly);
                    *(unsigned*)(outh + (size_t)row0 * NN + col) = uh;
                    *(unsigned*)(outl + (size_t)row0 * NN + col) = ul;
                }
                if (row1 < M) {
                    __nv_bfloat16 hx, lx, hy, ly;
                    bf16_split(v1x, hx, lx); bf16_split(v1y, hy, ly);
                    unsigned uh = pack2(hx, hy), ul = pack2(lx, ly);
                    *(unsigned*)(outh + (size_t)row1 * NN + col) = uh;
                    *(unsigned*)(outl + (size_t)row1 * NN + col) = ul;
                }
            } else {
                if (row0 < M)
                    *(float2*)(outf + (size_t)row0 * NN + col) = make_float2(v0x, v0y);
                if (row1 < M)
                    *(float2*)(outf + (size_t)row1 * NN + col) = make_float2(v1x, v1y);
            }
        }
    }
}

// ---------------- final layer + log_softmax ----------------------------------
__global__ void final_kernel(const float* __restrict__ agg,
                             const float* __restrict__ h,
                             const float* __restrict__ Wl,
                             const float* __restrict__ Wr,
                             const float* __restrict__ b,
                             float* __restrict__ out) {
    __shared__ float sWl[H2 * C_OUT], sWr[H2 * C_OUT], sb[C_OUT];
    for (int i = threadIdx.x; i < H2 * C_OUT; i += blockDim.x) {
        sWl[i] = Wl[i];
        sWr[i] = Wr[i];
    }
    if (threadIdx.x < C_OUT) sb[threadIdx.x] = b[threadIdx.x];
    __syncthreads();

    int n = blockIdx.x * blockDim.x + threadIdx.x;
    if (n >= N_NODES) return;

    float logit[C_OUT];
#pragma unroll
    for (int j = 0; j < C_OUT; j++) logit[j] = sb[j];

    const float* ar = agg + (size_t)n * H2;
    const float* hr = h   + (size_t)n * H2;
#pragma unroll 5
    for (int k = 0; k < H2; k++) {
        float a  = ar[k];
        float hh = hr[k];
#pragma unroll
        for (int j = 0; j < C_OUT; j++)
            logit[j] += a * sWl[k * C_OUT + j] + hh * sWr[k * C_OUT + j];
    }

    float mx = logit[0];
#pragma unroll
    for (int j = 1; j < C_OUT; j++) mx = fmaxf(mx, logit[j]);
    float s = 0.0f;
#pragma unroll
    for (int j = 0; j < C_OUT; j++) s += expf(logit[j] - mx);
    float lse = mx + logf(s);
#pragma unroll
    for (int j = 0; j < C_OUT; j++) out[(size_t)n * C_OUT + j] = logit[j] - lse;
}

// ---------------- launch ------------------------------------------------------
extern "C" void kernel_launch(void* const* d_in, const int* in_sizes, int n_in,
                              void* d_out, int out_size) {
    const float* x    = (const float*)d_in[0];
    const int*   ei   = (const int*)d_in[1];
    const float* W_l1 = (const float*)d_in[2];
    const float* b1   = (const float*)d_in[3];
    const float* W_r1 = (const float*)d_in[4];
    const float* W_l2 = (const float*)d_in[5];
    const float* b2   = (const float*)d_in[6];
    const float* W_r2 = (const float*)d_in[7];
    const float* W_l3 = (const float*)d_in[8];
    const float* b3   = (const float*)d_in[9];
    const float* W_r3 = (const float*)d_in[10];
    float* out = (float*)d_out;

    const int* src = ei;
    const int* dst = ei + N_EDGES;

    __nv_bfloat16 *xh, *xl, *a1h, *a1l, *h1h, *h1l, *a2h, *a2l;
    float *h2, *agg3;
    cudaGetSymbolAddress((void**)&xh,  g_xh);
    cudaGetSymbolAddress((void**)&xl,  g_xl);
    cudaGetSymbolAddress((void**)&a1h, g_a1h);
    cudaGetSymbolAddress((void**)&a1l, g_a1l);
    cudaGetSymbolAddress((void**)&h1h, g_h1h);
    cudaGetSymbolAddress((void**)&h1l, g_h1l);
    cudaGetSymbolAddress((void**)&a2h, g_a2h);
    cudaGetSymbolAddress((void**)&a2l, g_a2l);
    cudaGetSymbolAddress((void**)&h2,  g_h2);
    cudaGetSymbolAddress((void**)&agg3, g_agg3);

    zero_cnt_kernel<<<(N_NODES + 255) / 256, 256>>>();
    bucket_build_kernel<<<(N_EDGES + 255) / 256, 256>>>(src, dst);
    split_x_kernel<<<(N_NODES * F_IN / 4 + 255) / 256, 256>>>(x, xh, xl);

    const int aggBlocks = (N_NODES * 32 + 255) / 256;

    // layer 1: agg over x (bf16 hi/lo), GEMM -> h1 (split bf16 out)
    agg_bf16_kernel<F_IN><<<aggBlocks, 256>>>(xh, xl, a1h, a1l);
    {
        dim3 grid((H1 + 127) / 128, (N_NODES + 127) / 128);
        gemm_mma_ps<2, 8, 7, true><<<grid, 256>>>(
            a1h, a1l, xh, xl, W_l1, W_r1, b1,
            nullptr, h1h, h1l, N_NODES, F_IN, H1);
    }

    // layer 2: agg over h1 (bf16 hi/lo), GEMM -> h2 (fp32 out)
    agg_bf16_kernel<H1><<<aggBlocks, 256>>>(h1h, h1l, a2h, a2l);
    {
        dim3 grid((H2 + 63) / 64, (N_NODES + 127) / 128);
        gemm_mma_ps<2, 4, 6, false><<<grid, 256>>>(
            a2h, a2l, h1h, h1l, W_l2, W_r2, b2,
            h2, nullptr, nullptr, N_NODES, H1, H2);
    }

    // layer 3 + log_softmax (fp32 path)
    agg_kernel<H2><<<aggBlocks, 256>>>(h2, agg3);
    final_kernel<<<(N_NODES + 255) / 256, 256>>>(agg3, h2, W_l3, W_r3, b3, out);
}

// round 7
// speedup vs baseline: 1.3950x; 1.0428x over previous
#include <cuda_runtime.h>
#include <cuda_bf16.h>
#include <math.h>

#define N_NODES 100000
#define N_EDGES 1600000
#define F_IN   128
#define H1     200
#define H2     50
#define C_OUT  10
#define MAXDEG 128

// ---------------- scratch -----------------------------------------------------
__device__ int   g_cnt[N_NODES];
__device__ int   g_bucket[(size_t)N_NODES * MAXDEG];
__device__ __nv_bfloat16 g_xh  [(size_t)N_NODES * F_IN];
__device__ __nv_bfloat16 g_xl  [(size_t)N_NODES * F_IN];
__device__ __nv_bfloat16 g_a1h [(size_t)N_NODES * F_IN];
__device__ __nv_bfloat16 g_a1l [(size_t)N_NODES * F_IN];
__device__ float         g_h1f [(size_t)N_NODES * H1];
__device__ __nv_bfloat16 g_h1h [(size_t)N_NODES * H1];
__device__ __nv_bfloat16 g_h1l [(size_t)N_NODES * H1];
__device__ __nv_bfloat16 g_a2h [(size_t)N_NODES * H1];
__device__ __nv_bfloat16 g_a2l [(size_t)N_NODES * H1];
__device__ float g_h2  [(size_t)N_NODES * H2];
__device__ float g_agg3[(size_t)N_NODES * H2];

__device__ __forceinline__ void bf16_split(float x, __nv_bfloat16& h,
                                           __nv_bfloat16& l) {
    h = __float2bfloat16(x);
    l = __float2bfloat16(x - __bfloat162float(h));
}

__device__ __forceinline__ unsigned pack2(__nv_bfloat16 a, __nv_bfloat16 b) {
    __nv_bfloat162 p = __halves2bfloat162(a, b);
    return *reinterpret_cast<unsigned*>(&p);
}

// ---------------- bucket build ------------------------------------------------
__global__ void zero_cnt_kernel() {
    int i = blockIdx.x * blockDim.x + threadIdx.x;
    if (i < N_NODES) g_cnt[i] = 0;
}

__global__ void bucket_build_kernel(const int* __restrict__ src,
                                    const int* __restrict__ dst) {
    int e = blockIdx.x * blockDim.x + threadIdx.x;
    if (e >= N_EDGES) return;
    int d = dst[e];
    int p = atomicAdd(&g_cnt[d], 1);
    if (p < MAXDEG) g_bucket[(size_t)d * MAXDEG + p] = src[e];
}

// ---------------- one-time split of x ----------------------------------------
__global__ void split_x_kernel(const float* __restrict__ x,
                               __nv_bfloat16* __restrict__ xh,
                               __nv_bfloat16* __restrict__ xl) {
    int i = blockIdx.x * blockDim.x + threadIdx.x;
    if (i >= N_NODES * F_IN / 4) return;
    float4 v = ((const float4*)x)[i];
    __nv_bfloat16 h[4], l[4];
    bf16_split(v.x, h[0], l[0]);
    bf16_split(v.y, h[1], l[1]);
    bf16_split(v.z, h[2], l[2]);
    bf16_split(v.w, h[3], l[3]);
    uint2 uh, ul;
    uh.x = pack2(h[0], h[1]); uh.y = pack2(h[2], h[3]);
    ul.x = pack2(l[0], l[1]); ul.y = pack2(l[2], l[3]);
    *(uint2*)(xh + (size_t)i * 4) = uh;
    *(uint2*)(xl + (size_t)i * 4) = ul;
}

// ---------------- aggregation: fp32 gather (pure FMAX), split-bf16 output ----
template <int F>
__global__ void agg_split_kernel(const float* __restrict__ x,
                                 __nv_bfloat16* __restrict__ oh,
                                 __nv_bfloat16* __restrict__ ol) {
    constexpr int C4 = F / 4;               // float4 chunks per row
    constexpr int RV = (C4 + 31) / 32;

    int gwarp = (blockIdx.x * blockDim.x + threadIdx.x) >> 5;
    int lane  = threadIdx.x & 31;
    if (gwarp >= N_NODES) return;

    int c = g_cnt[gwarp];
    if (c > MAXDEG) c = MAXDEG;

    float4 m[RV];
#pragma unroll
    for (int r = 0; r < RV; r++)
        m[r] = make_float4(-INFINITY, -INFINITY, -INFINITY, -INFINITY);

    const int* bk = g_bucket + (size_t)gwarp * MAXDEG;
    int i = 0;
    for (; i + 3 < c; i += 4) {
        int s0 = bk[i], s1 = bk[i + 1], s2 = bk[i + 2], s3 = bk[i + 3];
        const float4* r0 = (const float4*)(x + (size_t)s0 * F);
        const float4* r1 = (const float4*)(x + (size_t)s1 * F);
        const float4* r2 = (const float4*)(x + (size_t)s2 * F);
        const float4* r3 = (const float4*)(x + (size_t)s3 * F);
#pragma unroll
        for (int r = 0; r < RV; r++) {
            int ch = lane + r * 32;
            if (ch < C4) {
                float4 v0 = r0[ch], v1 = r1[ch], v2 = r2[ch], v3 = r3[ch];
                m[r].x = fmaxf(m[r].x, fmaxf(fmaxf(v0.x, v1.x), fmaxf(v2.x, v3.x)));
                m[r].y = fmaxf(m[r].y, fmaxf(fmaxf(v0.y, v1.y), fmaxf(v2.y, v3.y)));
                m[r].z = fmaxf(m[r].z, fmaxf(fmaxf(v0.z, v1.z), fmaxf(v2.z, v3.z)));
                m[r].w = fmaxf(m[r].w, fmaxf(fmaxf(v0.w, v1.w), fmaxf(v2.w, v3.w)));
            }
        }
    }
    for (; i < c; i++) {
        const float4* r0 = (const float4*)(x + (size_t)bk[i] * F);
#pragma unroll
        for (int r = 0; r < RV; r++) {
            int ch = lane + r * 32;
            if (ch < C4) {
                float4 v0 = r0[ch];
                m[r].x = fmaxf(m[r].x, v0.x);
                m[r].y = fmaxf(m[r].y, v0.y);
                m[r].z = fmaxf(m[r].z, v0.z);
                m[r].w = fmaxf(m[r].w, v0.w);
            }
        }
    }

#pragma unroll
    for (int r = 0; r < RV; r++) {
        int ch = lane + r * 32;
        if (ch < C4) {
            float v[4] = {m[r].x, m[r].y, m[r].z, m[r].w};
            __nv_bfloat16 hh[4], ll[4];
#pragma unroll
            for (int q = 0; q < 4; q++) {
                float vv = (c == 0) ? 0.f : v[q];
                bf16_split(vv, hh[q], ll[q]);
            }
            uint2 uh, ul;
            uh.x = pack2(hh[0], hh[1]); uh.y = pack2(hh[2], hh[3]);
            ul.x = pack2(ll[0], ll[1]); ul.y = pack2(ll[2], ll[3]);
            *(uint2*)(oh + (size_t)gwarp * F + ch * 4) = uh;
            *(uint2*)(ol + (size_t)gwarp * F + ch * 4) = ul;
        }
    }
}

// ---------------- fp32 aggregation (layer 3, H2=50) --------------------------
template <int F>
__global__ void agg_kernel(const float* __restrict__ x, float* __restrict__ agg) {
    constexpr int C2 = F / 2;
    constexpr int RV = (C2 + 31) / 32;

    int gwarp = (blockIdx.x * blockDim.x + threadIdx.x) >> 5;
    int lane  = threadIdx.x & 31;
    if (gwarp >= N_NODES) return;

    int c = g_cnt[gwarp];
    if (c > MAXDEG) c = MAXDEG;

    float2 m[RV];
#pragma unroll
    for (int r = 0; r < RV; r++) { m[r].x = -INFINITY; m[r].y = -INFINITY; }

    const int* bk = g_bucket + (size_t)gwarp * MAXDEG;
    int i = 0;
    for (; i + 3 < c; i += 4) {
        int s0 = bk[i], s1 = bk[i + 1], s2 = bk[i + 2], s3 = bk[i + 3];
        const float2* r0 = (const float2*)(x + (size_t)s0 * F);
        const float2* r1 = (const float2*)(x + (size_t)s1 * F);
        const float2* r2 = (const float2*)(x + (size_t)s2 * F);
        const float2* r3 = (const float2*)(x + (size_t)s3 * F);
#pragma unroll
        for (int r = 0; r < RV; r++) {
            int ch = lane + r * 32;
            if (ch < C2) {
                float2 v0 = r0[ch], v1 = r1[ch], v2 = r2[ch], v3 = r3[ch];
                m[r].x = fmaxf(m[r].x, fmaxf(fmaxf(v0.x, v1.x), fmaxf(v2.x, v3.x)));
                m[r].y = fmaxf(m[r].y, fmaxf(fmaxf(v0.y, v1.y), fmaxf(v2.y, v3.y)));
            }
        }
    }
    for (; i < c; i++) {
        const float2* r0 = (const float2*)(x + (size_t)bk[i] * F);
#pragma unroll
        for (int r = 0; r < RV; r++) {
            int ch = lane + r * 32;
            if (ch < C2) {
                float2 v0 = r0[ch];
                m[r].x = fmaxf(m[r].x, v0.x);
                m[r].y = fmaxf(m[r].y, v0.y);
            }
        }
    }

    float2* out = (float2*)(agg + (size_t)gwarp * F);
#pragma unroll
    for (int r = 0; r < RV; r++) {
        int ch = lane + r * 32;
        if (ch < C2) out[ch] = (c == 0) ? make_float2(0.f, 0.f) : m[r];
    }
}

// ---------------- pre-split bf16 tensor-core dual GEMM -----------------------
#define MMA16816(d, a, b0, b1)                                                \
    asm volatile(                                                             \
        "mma.sync.aligned.m16n8k16.row.col.f32.bf16.bf16.f32 "                \
        "{%0,%1,%2,%3}, {%4,%5,%6,%7}, {%8,%9}, {%0,%1,%2,%3};"               \
        : "+f"(d[0]), "+f"(d[1]), "+f"(d[2]), "+f"(d[3])                      \
        : "r"(a[0]), "r"(a[1]), "r"(a[2]), "r"(a[3]), "r"(b0), "r"(b1))

// WM=4 fixed (BM=128). 256 threads, 8 warps (4 x WN). Double-buffered smem,
// one sync per 16-k tile. A arrives pre-split bf16; W converted in-kernel.
// SPLIT_OUT: write fp32 (outf) AND hi/lo bf16 (outh/outl).
template <int WN, int NT, int LOGBN, bool SPLIT_OUT>
__global__ __launch_bounds__(256, 2)
void gemm_mma_ps(const __nv_bfloat16* __restrict__ Ah1,
                 const __nv_bfloat16* __restrict__ Al1,
                 const __nv_bfloat16* __restrict__ Ah2,
                 const __nv_bfloat16* __restrict__ Al2,
                 const float* __restrict__ W1, const float* __restrict__ W2,
                 const float* __restrict__ bias,
                 float* __restrict__ outf,
                 __nv_bfloat16* __restrict__ outh,
                 __nv_bfloat16* __restrict__ outl,
                 int M, int K, int NN) {
    constexpr int WM = 4;
    constexpr int BM = 128;
    constexpr int BN = WN * NT * 8;
    constexpr int LDSTR = 24;            // conflict-free fragment loads
    constexpr int BU = (4 * BN) / 256;   // B load units per thread

    __shared__ __align__(16) __nv_bfloat16 Ash[2][BM * LDSTR];
    __shared__ __align__(16) __nv_bfloat16 Asl[2][BM * LDSTR];
    __shared__ __align__(16) __nv_bfloat16 Bsh[2][BN * LDSTR];
    __shared__ __align__(16) __nv_bfloat16 Bsl[2][BN * LDSTR];

    int tid = threadIdx.x;
    int lane = tid & 31;
    int wid = tid >> 5;
    int wm = wid % WM;
    int wn = wid / WM;
    int g  = lane >> 2;
    int tg = lane & 3;

    int rowBase = blockIdx.y * BM;
    int colBase = blockIdx.x * BN;

    int npt  = (K + 15) >> 4;
    int totT = 2 * npt;

    const int r_  = tid >> 1;
    const int kh_ = (tid & 1) * 8;
    const int aRow = rowBase + r_;

    float acc[2][NT][4];
#pragma unroll
    for (int mt = 0; mt < 2; mt++)
#pragma unroll
        for (int nt = 0; nt < NT; nt++)
#pragma unroll
            for (int q = 0; q < 4; q++) acc[mt][nt][q] = 0.f;

    uint4 pAh, pAl;
    float pB[BU][4];

    auto prefetch = [&](int t) {
        const __nv_bfloat16 *Ah, *Al; const float* W; int ko;
        if (t < npt) { Ah = Ah1; Al = Al1; W = W1; ko = t << 4; }
        else         { Ah = Ah2; Al = Al2; W = W2; ko = (t - npt) << 4; }

        int gk = ko + kh_;
        pAh = make_uint4(0u, 0u, 0u, 0u);
        pAl = make_uint4(0u, 0u, 0u, 0u);
        if (aRow < M && gk + 8 <= K) {
            pAh = *(const uint4*)(Ah + (size_t)aRow * K + gk);
            pAl = *(const uint4*)(Al + (size_t)aRow * K + gk);
        }
#pragma unroll
        for (int bu = 0; bu < BU; bu++) {
            int u = tid + bu * 256;
            int n = u & (BN - 1);
            int kq = (u >> LOGBN) << 2;
            int gn = colBase + n;
#pragma unroll
            for (int q = 0; q < 4; q++) {
                int gk2 = ko + kq + q;
                pB[bu][q] = (gn < NN && gk2 < K) ? W[(size_t)gk2 * NN + gn] : 0.f;
            }
        }
    };

    auto sts = [&](int buf) {
        *(uint4*)&Ash[buf][r_ * LDSTR + kh_] = pAh;
        *(uint4*)&Asl[buf][r_ * LDSTR + kh_] = pAl;
#pragma unroll
        for (int bu = 0; bu < BU; bu++) {
            int u = tid + bu * 256;
            int n = u & (BN - 1);
            int kq = (u >> LOGBN) << 2;
            __nv_bfloat16 h[4], l[4];
#pragma unroll
            for (int q = 0; q < 4; q++) bf16_split(pB[bu][q], h[q], l[q]);
            uint2 uh, ul;
            uh.x = pack2(h[0], h[1]); uh.y = pack2(h[2], h[3]);
            ul.x = pack2(l[0], l[1]); ul.y = pack2(l[2], l[3]);
            *(uint2*)&Bsh[buf][n * LDSTR + kq] = uh;
            *(uint2*)&Bsl[buf][n * LDSTR + kq] = ul;
        }
    };

    auto compute = [&](int buf) {
        unsigned afh[2][4], afl[2][4];
#pragma unroll
        for (int mt = 0; mt < 2; mt++) {
            int r0 = wm * 32 + mt * 16 + g;
            afh[mt][0] = *(const unsigned*)&Ash[buf][(r0)     * LDSTR + 2 * tg];
            afh[mt][1] = *(const unsigned*)&Ash[buf][(r0 + 8) * LDSTR + 2 * tg];
            afh[mt][2] = *(const unsigned*)&Ash[buf][(r0)     * LDSTR + 2 * tg + 8];
            afh[mt][3] = *(const unsigned*)&Ash[buf][(r0 + 8) * LDSTR + 2 * tg + 8];
            afl[mt][0] = *(const unsigned*)&Asl[buf][(r0)     * LDSTR + 2 * tg];
            afl[mt][1] = *(const unsigned*)&Asl[buf][(r0 + 8) * LDSTR + 2 * tg];
            afl[mt][2] = *(const unsigned*)&Asl[buf][(r0)     * LDSTR + 2 * tg + 8];
            afl[mt][3] = *(const unsigned*)&Asl[buf][(r0 + 8) * LDSTR + 2 * tg + 8];
        }
#pragma unroll
        for (int nt = 0; nt < NT; nt++) {
            int c0 = (wn * NT + nt) * 8 + g;
            unsigned bh0 = *(const unsigned*)&Bsh[buf][c0 * LDSTR + 2 * tg];
            unsigned bh1 = *(const unsigned*)&Bsh[buf][c0 * LDSTR + 2 * tg + 8];
            unsigned bl0 = *(const unsigned*)&Bsl[buf][c0 * LDSTR + 2 * tg];
            unsigned bl1 = *(const unsigned*)&Bsl[buf][c0 * LDSTR + 2 * tg + 8];
#pragma unroll
            for (int mt = 0; mt < 2; mt++) {
                MMA16816(acc[mt][nt], afh[mt], bh0, bh1);
                MMA16816(acc[mt][nt], afh[mt], bl0, bl1);
                MMA16816(acc[mt][nt], afl[mt], bh0, bh1);
            }
        }
    };

    prefetch(0);
    sts(0);
    __syncthreads();

    for (int t = 0; t < totT; t++) {
        int buf = t & 1;
        if (t + 1 < totT) prefetch(t + 1);
        compute(buf);
        if (t + 1 < totT) sts(buf ^ 1);
        __syncthreads();
    }

    // ---- epilogue ----
#pragma unroll
    for (int mt = 0; mt < 2; mt++) {
#pragma unroll
        for (int nt = 0; nt < NT; nt++) {
            int col = colBase + (wn * NT + nt) * 8 + 2 * tg;
            if (col >= NN) continue;
            float2 bv = *(const float2*)(bias + col);
            int row0 = rowBase + wm * 32 + mt * 16 + g;
            int row1 = row0 + 8;
            float v0x = acc[mt][nt][0] + bv.x, v0y = acc[mt][nt][1] + bv.y;
            float v1x = acc[mt][nt][2] + bv.x, v1y = acc[mt][nt][3] + bv.y;
            if (row0 < M) {
                if (SPLIT_OUT) {
                    __nv_bfloat16 hx, lx, hy, ly;
                    bf16_split(v0x, hx, lx); bf16_split(v0y, hy, ly);
                    *(unsigned*)(outh + (size_t)row0 * NN + col) = pack2(hx, hy);
                    *(unsigned*)(outl + (size_t)row0 * NN + col) = pack2(lx, ly);
                }
                *(float2*)(outf + (size_t)row0 * NN + col) = make_float2(v0x, v0y);
            }
            if (row1 < M) {
                if (SPLIT_OUT) {
                    __nv_bfloat16 hx, lx, hy, ly;
                    bf16_split(v1x, hx, lx); bf16_split(v1y, hy, ly);
                    *(unsigned*)(outh + (size_t)row1 * NN + col) = pack2(hx, hy);
                    *(unsigned*)(outl + (size_t)row1 * NN + col) = pack2(lx, ly);
                }
                *(float2*)(outf + (size_t)row1 * NN + col) = make_float2(v1x, v1y);
            }
        }
    }
}

// ---------------- final layer + log_softmax ----------------------------------
__global__ void final_kernel(const float* __restrict__ agg,
                             const float* __restrict__ h,
                             const float* __restrict__ Wl,
                             const float* __restrict__ Wr,
                             const float* __restrict__ b,
                             float* __restrict__ out) {
    __shared__ float sWl[H2 * C_OUT], sWr[H2 * C_OUT], sb[C_OUT];
    for (int i = threadIdx.x; i < H2 * C_OUT; i += blockDim.x) {
        sWl[i] = Wl[i];
        sWr[i] = Wr[i];
    }
    if (threadIdx.x < C_OUT) sb[threadIdx.x] = b[threadIdx.x];
    __syncthreads();

    int n = blockIdx.x * blockDim.x + threadIdx.x;
    if (n >= N_NODES) return;

    float logit[C_OUT];
#pragma unroll
    for (int j = 0; j < C_OUT; j++) logit[j] = sb[j];

    const float* ar = agg + (size_t)n * H2;
    const float* hr = h   + (size_t)n * H2;
#pragma unroll 5
    for (int k = 0; k < H2; k++) {
        float a  = ar[k];
        float hh = hr[k];
#pragma unroll
        for (int j = 0; j < C_OUT; j++)
            logit[j] += a * sWl[k * C_OUT + j] + hh * sWr[k * C_OUT + j];
    }

    float mx = logit[0];
#pragma unroll
    for (int j = 1; j < C_OUT; j++) mx = fmaxf(mx, logit[j]);
    float s = 0.0f;
#pragma unroll
    for (int j = 0; j < C_OUT; j++) s += expf(logit[j] - mx);
    float lse = mx + logf(s);
#pragma unroll
    for (int j = 0; j < C_OUT; j++) out[(size_t)n * C_OUT + j] = logit[j] - lse;
}

// ---------------- launch ------------------------------------------------------
extern "C" void kernel_launch(void* const* d_in, const int* in_sizes, int n_in,
                              void* d_out, int out_size) {
    const float* x    = (const float*)d_in[0];
    const int*   ei   = (const int*)d_in[1];
    const float* W_l1 = (const float*)d_in[2];
    const float* b1   = (const float*)d_in[3];
    const float* W_r1 = (const float*)d_in[4];
    const float* W_l2 = (const float*)d_in[5];
    const float* b2   = (const float*)d_in[6];
    const float* W_r2 = (const float*)d_in[7];
    const float* W_l3 = (const float*)d_in[8];
    const float* b3   = (const float*)d_in[9];
    const float* W_r3 = (const float*)d_in[10];
    float* out = (float*)d_out;

    const int* src = ei;
    const int* dst = ei + N_EDGES;

    __nv_bfloat16 *xh, *xl, *a1h, *a1l, *h1h, *h1l, *a2h, *a2l;
    float *h1f, *h2, *agg3;
    cudaGetSymbolAddress((void**)&xh,  g_xh);
    cudaGetSymbolAddress((void**)&xl,  g_xl);
    cudaGetSymbolAddress((void**)&a1h, g_a1h);
    cudaGetSymbolAddress((void**)&a1l, g_a1l);
    cudaGetSymbolAddress((void**)&h1f, g_h1f);
    cudaGetSymbolAddress((void**)&h1h, g_h1h);
    cudaGetSymbolAddress((void**)&h1l, g_h1l);
    cudaGetSymbolAddress((void**)&a2h, g_a2h);
    cudaGetSymbolAddress((void**)&a2l, g_a2l);
    cudaGetSymbolAddress((void**)&h2,  g_h2);
    cudaGetSymbolAddress((void**)&agg3, g_agg3);

    zero_cnt_kernel<<<(N_NODES + 255) / 256, 256>>>();
    bucket_build_kernel<<<(N_EDGES + 255) / 256, 256>>>(src, dst);
    split_x_kernel<<<(N_NODES * F_IN / 4 + 255) / 256, 256>>>(x, xh, xl);

    const int aggBlocks = (N_NODES * 32 + 255) / 256;

    // layer 1: agg over fp32 x -> split a1; GEMM -> h1 fp32 + split
    agg_split_kernel<F_IN><<<aggBlocks, 256>>>(x, a1h, a1l);
    {
        dim3 grid((H1 + 127) / 128, (N_NODES + 127) / 128);
        gemm_mma_ps<2, 8, 7, true><<<grid, 256>>>(
            a1h, a1l, xh, xl, W_l1, W_r1, b1,
            h1f, h1h, h1l, N_NODES, F_IN, H1);
    }

    // layer 2: agg over fp32 h1 -> split a2; GEMM -> h2 fp32
    agg_split_kernel<H1><<<aggBlocks, 256>>>(h1f, a2h, a2l);
    {
        dim3 grid((H2 + 63) / 64, (N_NODES + 127) / 128);
        gemm_mma_ps<2, 4, 6, false><<<grid, 256>>>(
            a2h, a2l, h1h, h1l, W_l2, W_r2, b2,
            h2, nullptr, nullptr, N_NODES, H1, H2);
    }

    // layer 3 + log_softmax (fp32 path)
    agg_kernel<H2><<<aggBlocks, 256>>>(h2, agg3);
    final_kernel<<<(N_NODES + 255) / 256, 256>>>(agg3, h2, W_l3, W_r3, b3, out);
}